// round 11
// baseline (speedup 1.0000x reference)
#include <cuda_runtime.h>
#include <cuda_fp16.h>

// Problem constants
#define Bn   64
#define Rn   4608
#define Cn   32
#define INn  8
#define OUTn 16
#define RCHUNK 64
#define NCHUNK 72    // Rn / RCHUNK
#define RPASS  128
#define NSPLIT 36    // Rn / RPASS

typedef unsigned long long ull;

// Scratch (device globals; allocation-free per harness rules)
// u_hat layout: [c][r][h(2)][b(64)] of uint4 (8 fp16 each) -> dense 512B warp accesses
static __device__ uint4  g_uhat4[(size_t)Cn * Rn * 2 * Bn];          // 302 MB
static __device__ float4 g_xT4[(size_t)Rn * 2 * Bn];                 // x transposed: [r][h][b] float4
static __device__ float  g_part[(size_t)Cn * NCHUNK * Bn * OUTn];    // iter-1 partial sums (exact fp32)
static __device__ float  g_red[(size_t)Cn * NSPLIT * Bn * 17];       // pass partials (n[16], d)
static __device__ float  g_v1[(size_t)Bn * Cn * OUTn];
static __device__ float  g_vcur[(size_t)Bn * Cn * OUTn];             // current logit vector

// ---- packed f32x2 helpers ----
__device__ __forceinline__ ull pk2(float lo, float hi) {
    ull r;
    asm("mov.b64 %0, {%1, %2};" : "=l"(r) : "f"(lo), "f"(hi));
    return r;
}
__device__ __forceinline__ ull ffma2(ull a, ull b, ull c) {
    ull d;
    asm("fma.rn.f32x2 %0, %1, %2, %3;" : "=l"(d) : "l"(a), "l"(b), "l"(c));
    return d;
}
__device__ __forceinline__ ull fadd2(ull a, ull b) {
    ull d;
    asm("add.rn.f32x2 %0, %1, %2;" : "=l"(d) : "l"(a), "l"(b));
    return d;
}
__device__ __forceinline__ float2 upk2(ull v) {
    float lo, hi;
    asm("mov.b64 {%0, %1}, %2;" : "=f"(lo), "=f"(hi) : "l"(v));
    return make_float2(lo, hi);
}

// ============================================================================
// k0: transpose x (64 b, 9216 float4-cols) -> xT (9216 rows, 64 b).
// f0_base: column-slice offset so the transpose can be issued as several
// launches (puts k1_uhat at ncu's -s 5 capture slot; same total work).
// ============================================================================
__global__ void __launch_bounds__(256)
k0_transpose(const float4* __restrict__ x4, int f0_base) {
    __shared__ float4 tile[32][33];
    const int f0 = (f0_base + blockIdx.x) * 32;
    const int b0 = blockIdx.y * 32;
    const int tx = threadIdx.x;
    const int ty0 = threadIdx.y;
    #pragma unroll
    for (int j = 0; j < 4; j++) {
        int ty = ty0 * 4 + j;
        tile[ty][tx] = x4[(size_t)(b0 + ty) * (Rn * 2) + f0 + tx];
    }
    __syncthreads();
    #pragma unroll
    for (int j = 0; j < 4; j++) {
        int ty = ty0 * 4 + j;
        g_xT4[(size_t)(f0 + ty) * Bn + b0 + tx] = tile[tx][ty];
    }
}

// ============================================================================
// k1 (exact R7 body — the measured-best config): u_hat fp16 (dense) + exact
// fp32 iter-1 partials. 2-BATCH BLOCKED: block 256 = 8 warps; warp = 8-route
// group, lane = b-pair (lane, lane+32). Each smem W value feeds 2 FFMA2.
// ============================================================================
__global__ void __launch_bounds__(256)
k1_uhat(const float* __restrict__ w) {
    const int c     = blockIdx.x;
    const int chunk = blockIdx.y;
    const int r0    = chunk * RCHUNK;
    const int tid   = threadIdx.x;
    const int warp  = tid >> 5;        // rgroup 0..7 (8 routes each)
    const int lane  = tid & 31;        // b0 = lane, b1 = lane + 32

    __shared__ float sW[RCHUNK * 128];   // 32 KB; reused for the reduction

    {
        const float4* wg = reinterpret_cast<const float4*>(w);
        float4*       ws = reinterpret_cast<float4*>(sW);
        #pragma unroll
        for (int t = tid; t < RCHUNK * 32; t += 256) {
            int rr = t >> 5;
            int q  = t & 31;
            ws[rr * 32 + q] = wg[((size_t)(r0 + rr) * Cn + c) * 32 + q];
        }
    }
    __syncthreads();

    ull sacc0[8], sacc1[8];            // packed f32x2 iter-1 accumulators
    #pragma unroll
    for (int j = 0; j < 8; j++) { sacc0[j] = 0ull; sacc1[j] = 0ull; }

    for (int k = 0; k < 8; k++) {
        const int rr = warp * 8 + k;
        const int r  = r0 + rr;

        // x rows for both batches (dense across lanes, L2-hot)
        float4 xa0 = g_xT4[((size_t)r * 2 + 0) * Bn + lane];
        float4 xb0 = g_xT4[((size_t)r * 2 + 1) * Bn + lane];
        float4 xa1 = g_xT4[((size_t)r * 2 + 0) * Bn + lane + 32];
        float4 xb1 = g_xT4[((size_t)r * 2 + 1) * Bn + lane + 32];
        float xv0[8] = {xa0.x, xa0.y, xa0.z, xa0.w, xb0.x, xb0.y, xb0.z, xb0.w};
        float xv1[8] = {xa1.x, xa1.y, xa1.z, xa1.w, xb1.x, xb1.y, xb1.z, xb1.w};

        ull acc0[8], acc1[8];
        #pragma unroll
        for (int j = 0; j < 8; j++) { acc0[j] = 0ull; acc1[j] = 0ull; }

        const ull* wr = reinterpret_cast<const ull*>(sW + rr * 128);
        #pragma unroll
        for (int i = 0; i < 8; i++) {
            ull x20 = pk2(xv0[i], xv0[i]);
            ull x21 = pk2(xv1[i], xv1[i]);
            #pragma unroll
            for (int j = 0; j < 8; j++) {
                ull wv = wr[i * 8 + j];            // broadcast LDS.64, reused 2x
                acc0[j] = ffma2(x20, wv, acc0[j]);
                acc1[j] = ffma2(x21, wv, acc1[j]);
            }
        }

        union { __half2 h[8]; uint4 q[2]; } cv0, cv1;
        #pragma unroll
        for (int j = 0; j < 8; j++) {
            sacc0[j] = fadd2(sacc0[j], acc0[j]);
            sacc1[j] = fadd2(sacc1[j], acc1[j]);
            float2 u0 = upk2(acc0[j]);
            float2 u1 = upk2(acc1[j]);
            cv0.h[j] = __floats2half2_rn(u0.x, u0.y);
            cv1.h[j] = __floats2half2_rn(u1.x, u1.y);
        }
        // dense stores: [c][r][h][b]
        size_t base = ((size_t)(c * Rn + r) * 2) * Bn + lane;
        g_uhat4[base]           = cv0.q[0];
        g_uhat4[base + Bn]      = cv0.q[1];
        g_uhat4[base + 32]      = cv1.q[0];
        g_uhat4[base + Bn + 32] = cv1.q[1];
    }

    // ---- reduce iter-1 partials over the 8 rgroups (fixed order) ----
    __syncthreads();                    // done with sW contents
    float* sred = sW;                   // [8 rg][64 b][16 o] = 32 KB
    #pragma unroll
    for (int j = 0; j < 8; j++) {
        float2 u0 = upk2(sacc0[j]);
        float2 u1 = upk2(sacc1[j]);
        sred[((size_t)warp * Bn + lane) * OUTn + 2 * j]          = u0.x;
        sred[((size_t)warp * Bn + lane) * OUTn + 2 * j + 1]      = u0.y;
        sred[((size_t)warp * Bn + lane + 32) * OUTn + 2 * j]     = u1.x;
        sred[((size_t)warp * Bn + lane + 32) * OUTn + 2 * j + 1] = u1.y;
    }
    __syncthreads();
    #pragma unroll
    for (int s = 0; s < 4; s++) {
        int idx = tid * 4 + s;
        int b_ = idx >> 4, o_ = idx & 15;
        float acc = 0.f;
        #pragma unroll
        for (int rg = 0; rg < 8; rg++)
            acc += sred[((size_t)rg * Bn + b_) * OUTn + o_];
        g_part[(((size_t)c * NCHUNK + chunk) * Bn + b_) * OUTn + o_] = acc;
    }
}

// ============================================================================
// kf_v1: v1 = squash(mean_r u_r) per (b,c); seeds g_vcur = v1.
// ============================================================================
__global__ void __launch_bounds__(32)
kf_v1() {
    const int bc = blockIdx.x;
    const int b  = bc >> 5;
    const int c  = bc & 31;
    const int t  = threadIdx.x;

    float acc = 0.f;
    if (t < OUTn) {
        for (int ch = 0; ch < NCHUNK; ch++)
            acc += g_part[(((size_t)c * NCHUNK + ch) * Bn + b) * OUTn + t];
    }
    float val = (t < OUTn) ? acc * (1.0f / Rn) : 0.f;
    float sq = val * val;
    #pragma unroll
    for (int off = 16; off; off >>= 1) sq += __shfl_xor_sync(0xffffffffu, sq, off);
    float coef = (sq / (1.f + sq)) * rsqrtf(sq + 1e-8f);
    float v = val * coef;
    if (t < OUTn) {
        g_v1[(size_t)bc * OUTn + t]   = v;
        g_vcur[(size_t)bc * OUTn + t] = v;
    }
}

// ============================================================================
// k2p (exact R7 body, measured 54.2us / DRAM 72%): streaming routing pass,
// o-split across lane pairs. CTA = (c, 128-r slab).
// ============================================================================
__global__ void __launch_bounds__(256)
k2p() {
    const int c     = blockIdx.x;
    const int split = blockIdx.y;
    const int tid   = threadIdx.x;
    const int warp  = tid >> 5;
    const int lane  = tid & 31;
    const int rg    = warp >> 2;            // 0..1 (64 r each)
    const int bq    = warp & 3;             // 0..3
    const int hh    = lane >> 4;            // 0/1 (which 8 outputs)
    const int b     = bq * 16 + (lane & 15);

    __shared__ float sV[Bn * OUTn];
    __shared__ float sRed[2][Bn][18];

    for (int t = tid; t < Bn * OUTn; t += 256) {
        int b_ = t >> 4, o_ = t & 15;
        sV[t] = g_vcur[((size_t)b_ * Cn + c) * OUTn + o_];
    }
    __syncthreads();

    float v[8];
    #pragma unroll
    for (int j = 0; j < 8; j++) v[j] = sV[b * OUTn + hh * 8 + j];

    float d = 0.f;
    float n[8];
    #pragma unroll
    for (int j = 0; j < 8; j++) n[j] = 0.f;

    const int rbase = split * RPASS + rg * 64;
    size_t base = ((size_t)(c * Rn + rbase) * 2 + hh) * Bn + b;

    #pragma unroll 8
    for (int k = 0; k < 64; k++) {
        uint4 q = g_uhat4[base + (size_t)k * 2 * Bn];
        union { __half2 h[4]; uint4 q4; } cv;
        cv.q4 = q;
        float u[8];
        #pragma unroll
        for (int j = 0; j < 4; j++) {
            float2 f = __half22float2(cv.h[j]);
            u[2 * j]     = f.x;
            u[2 * j + 1] = f.y;
        }
        float t = 0.f;
        #pragma unroll
        for (int j = 0; j < 8; j++) t = fmaf(u[j], v[j], t);
        t += __shfl_xor_sync(0xffffffffu, t, 16);       // full 16-dim dot
        float e = __expf(t);
        d += e;
        #pragma unroll
        for (int j = 0; j < 8; j++) n[j] = fmaf(e, u[j], n[j]);
    }

    #pragma unroll
    for (int j = 0; j < 8; j++) sRed[rg][b][hh * 8 + j] = n[j];
    if (hh == 0) sRed[rg][b][16] = d;
    __syncthreads();

    for (int t = tid; t < Bn * 17; t += 256) {
        int b_ = t / 17, o_ = t % 17;
        g_red[(((size_t)c * NSPLIT + split) * Bn + b_) * 17 + o_] =
            sRed[0][b_][o_] + sRed[1][b_][o_];
    }
}

// ============================================================================
// kf_fin: reduce slab partials -> softmax-weighted sum -> squash.
// mode 0: g_vcur = v1 + v2.  mode 1: write v3 to out.
// ============================================================================
__global__ void __launch_bounds__(32)
kf_fin(int mode, float* __restrict__ out) {
    const int bc = blockIdx.x;
    const int b  = bc >> 5;
    const int c  = bc & 31;
    const int t  = threadIdx.x;

    float acc = 0.f;
    if (t < 17) {
        for (int s = 0; s < NSPLIT; s++)
            acc += g_red[(((size_t)c * NSPLIT + s) * Bn + b) * 17 + t];
    }
    float D = __shfl_sync(0xffffffffu, acc, 16);
    float val = (t < OUTn) ? acc / D : 0.f;
    float sq = val * val;
    #pragma unroll
    for (int off = 16; off; off >>= 1) sq += __shfl_xor_sync(0xffffffffu, sq, off);
    float coef = (sq / (1.f + sq)) * rsqrtf(sq + 1e-8f);
    float v = val * coef;
    if (t < OUTn) {
        if (mode == 0)
            g_vcur[(size_t)bc * OUTn + t] = g_v1[(size_t)bc * OUTn + t] + v;
        else
            out[(size_t)bc * OUTn + t] = v;
    }
}

// ============================================================================
extern "C" void kernel_launch(void* const* d_in, const int* in_sizes, int n_in,
                              void* d_out, int out_size) {
    const float* x = (const float*)d_in[0];           // (64, 4608, 8)
    const float* w = (const float*)d_in[1];           // (4608, 32, 8, 16)
    float* out = (float*)d_out;                       // (64, 32, 16)

    // Transpose issued as 5 slice launches (58+58+58+58+56 = 288 col-tiles)
    // so that launch index 5 (ncu -s 5 -c 1) is k1_uhat, not k2p.
    k0_transpose<<<dim3(58, Bn / 32), dim3(32, 8)>>>((const float4*)x, 0);
    k0_transpose<<<dim3(58, Bn / 32), dim3(32, 8)>>>((const float4*)x, 58);
    k0_transpose<<<dim3(58, Bn / 32), dim3(32, 8)>>>((const float4*)x, 116);
    k0_transpose<<<dim3(58, Bn / 32), dim3(32, 8)>>>((const float4*)x, 174);
    k0_transpose<<<dim3(56, Bn / 32), dim3(32, 8)>>>((const float4*)x, 232);
    k1_uhat<<<dim3(Cn, NCHUNK), 256>>>(w);
    kf_v1<<<Bn * Cn, 32>>>();
    k2p<<<dim3(Cn, NSPLIT), 256>>>();
    kf_fin<<<Bn * Cn, 32>>>(0, out);
    k2p<<<dim3(Cn, NSPLIT), 256>>>();
    kf_fin<<<Bn * Cn, 32>>>(1, out);
}

// round 12
// speedup vs baseline: 1.0531x; 1.0531x over previous
#include <cuda_runtime.h>
#include <cuda_fp16.h>

// Problem constants
#define Bn   64
#define Rn   4608
#define Cn   32
#define INn  8
#define OUTn 16
#define RCHUNK 64
#define NCHUNK 72    // Rn / RCHUNK
#define RPASS  256
#define NSPLIT 18    // Rn / RPASS

typedef unsigned long long ull;

// Scratch (device globals; allocation-free per harness rules)
// u_hat layout: [c][r][h(2)][b(64)] of uint4 (8 fp16 each) -> dense 512B warp accesses
static __device__ uint4  g_uhat4[(size_t)Cn * Rn * 2 * Bn];          // 302 MB
static __device__ float4 g_xT4[(size_t)Rn * 2 * Bn];                 // x transposed: [r][h][b] float4
static __device__ float  g_part[(size_t)Cn * NCHUNK * Bn * OUTn];    // iter-1 partial sums (exact fp32)
static __device__ float  g_red[(size_t)Cn * NSPLIT * Bn * 17];       // pass partials (n[16], d)
static __device__ float  g_v1[(size_t)Bn * Cn * OUTn];
static __device__ float  g_vcur[(size_t)Bn * Cn * OUTn];             // current logit vector

// ---- packed f32x2 helpers ----
__device__ __forceinline__ ull pk2(float lo, float hi) {
    ull r;
    asm("mov.b64 %0, {%1, %2};" : "=l"(r) : "f"(lo), "f"(hi));
    return r;
}
__device__ __forceinline__ ull ffma2(ull a, ull b, ull c) {
    ull d;
    asm("fma.rn.f32x2 %0, %1, %2, %3;" : "=l"(d) : "l"(a), "l"(b), "l"(c));
    return d;
}
__device__ __forceinline__ ull fadd2(ull a, ull b) {
    ull d;
    asm("add.rn.f32x2 %0, %1, %2;" : "=l"(d) : "l"(a), "l"(b));
    return d;
}
__device__ __forceinline__ float2 upk2(ull v) {
    float lo, hi;
    asm("mov.b64 {%0, %1}, %2;" : "=f"(lo), "=f"(hi) : "l"(v));
    return make_float2(lo, hi);
}

// ============================================================================
// k0: transpose x (64 b, 9216 float4-cols) -> xT (9216 rows, 64 b).
// ============================================================================
__global__ void __launch_bounds__(256)
k0_transpose(const float4* __restrict__ x4) {
    __shared__ float4 tile[32][33];
    const int f0 = blockIdx.x * 32;
    const int b0 = blockIdx.y * 32;
    const int tx = threadIdx.x;
    const int ty0 = threadIdx.y;
    #pragma unroll
    for (int j = 0; j < 4; j++) {
        int ty = ty0 * 4 + j;
        tile[ty][tx] = x4[(size_t)(b0 + ty) * (Rn * 2) + f0 + tx];
    }
    __syncthreads();
    #pragma unroll
    for (int j = 0; j < 4; j++) {
        int ty = ty0 * 4 + j;
        g_xT4[(size_t)(f0 + ty) * Bn + b0 + tx] = tile[tx][ty];
    }
}

// ============================================================================
// k1 (exact R7 body — measured-best): u_hat fp16 (dense) + exact fp32
// iter-1 partials. 2-BATCH BLOCKED: block 256 = 8 warps; warp = 8-route
// group, lane = b-pair (lane, lane+32). Each smem W value feeds 2 FFMA2.
// ============================================================================
__global__ void __launch_bounds__(256)
k1_uhat(const float* __restrict__ w) {
    const int c     = blockIdx.x;
    const int chunk = blockIdx.y;
    const int r0    = chunk * RCHUNK;
    const int tid   = threadIdx.x;
    const int warp  = tid >> 5;        // rgroup 0..7 (8 routes each)
    const int lane  = tid & 31;        // b0 = lane, b1 = lane + 32

    __shared__ float sW[RCHUNK * 128];   // 32 KB; reused for the reduction

    {
        const float4* wg = reinterpret_cast<const float4*>(w);
        float4*       ws = reinterpret_cast<float4*>(sW);
        #pragma unroll
        for (int t = tid; t < RCHUNK * 32; t += 256) {
            int rr = t >> 5;
            int q  = t & 31;
            ws[rr * 32 + q] = wg[((size_t)(r0 + rr) * Cn + c) * 32 + q];
        }
    }
    __syncthreads();

    ull sacc0[8], sacc1[8];            // packed f32x2 iter-1 accumulators
    #pragma unroll
    for (int j = 0; j < 8; j++) { sacc0[j] = 0ull; sacc1[j] = 0ull; }

    for (int k = 0; k < 8; k++) {
        const int rr = warp * 8 + k;
        const int r  = r0 + rr;

        // x rows for both batches (dense across lanes, L2-hot)
        float4 xa0 = g_xT4[((size_t)r * 2 + 0) * Bn + lane];
        float4 xb0 = g_xT4[((size_t)r * 2 + 1) * Bn + lane];
        float4 xa1 = g_xT4[((size_t)r * 2 + 0) * Bn + lane + 32];
        float4 xb1 = g_xT4[((size_t)r * 2 + 1) * Bn + lane + 32];
        float xv0[8] = {xa0.x, xa0.y, xa0.z, xa0.w, xb0.x, xb0.y, xb0.z, xb0.w};
        float xv1[8] = {xa1.x, xa1.y, xa1.z, xa1.w, xb1.x, xb1.y, xb1.z, xb1.w};

        ull acc0[8], acc1[8];
        #pragma unroll
        for (int j = 0; j < 8; j++) { acc0[j] = 0ull; acc1[j] = 0ull; }

        const ull* wr = reinterpret_cast<const ull*>(sW + rr * 128);
        #pragma unroll
        for (int i = 0; i < 8; i++) {
            ull x20 = pk2(xv0[i], xv0[i]);
            ull x21 = pk2(xv1[i], xv1[i]);
            #pragma unroll
            for (int j = 0; j < 8; j++) {
                ull wv = wr[i * 8 + j];            // broadcast LDS.64, reused 2x
                acc0[j] = ffma2(x20, wv, acc0[j]);
                acc1[j] = ffma2(x21, wv, acc1[j]);
            }
        }

        union { __half2 h[8]; uint4 q[2]; } cv0, cv1;
        #pragma unroll
        for (int j = 0; j < 8; j++) {
            sacc0[j] = fadd2(sacc0[j], acc0[j]);
            sacc1[j] = fadd2(sacc1[j], acc1[j]);
            float2 u0 = upk2(acc0[j]);
            float2 u1 = upk2(acc1[j]);
            cv0.h[j] = __floats2half2_rn(u0.x, u0.y);
            cv1.h[j] = __floats2half2_rn(u1.x, u1.y);
        }
        // dense stores: [c][r][h][b]
        size_t base = ((size_t)(c * Rn + r) * 2) * Bn + lane;
        g_uhat4[base]           = cv0.q[0];
        g_uhat4[base + Bn]      = cv0.q[1];
        g_uhat4[base + 32]      = cv1.q[0];
        g_uhat4[base + Bn + 32] = cv1.q[1];
    }

    // ---- reduce iter-1 partials over the 8 rgroups (fixed order) ----
    __syncthreads();                    // done with sW contents
    float* sred = sW;                   // [8 rg][64 b][16 o] = 32 KB
    #pragma unroll
    for (int j = 0; j < 8; j++) {
        float2 u0 = upk2(sacc0[j]);
        float2 u1 = upk2(sacc1[j]);
        sred[((size_t)warp * Bn + lane) * OUTn + 2 * j]          = u0.x;
        sred[((size_t)warp * Bn + lane) * OUTn + 2 * j + 1]      = u0.y;
        sred[((size_t)warp * Bn + lane + 32) * OUTn + 2 * j]     = u1.x;
        sred[((size_t)warp * Bn + lane + 32) * OUTn + 2 * j + 1] = u1.y;
    }
    __syncthreads();
    #pragma unroll
    for (int s = 0; s < 4; s++) {
        int idx = tid * 4 + s;
        int b_ = idx >> 4, o_ = idx & 15;
        float acc = 0.f;
        #pragma unroll
        for (int rg = 0; rg < 8; rg++)
            acc += sred[((size_t)rg * Bn + b_) * OUTn + o_];
        g_part[(((size_t)c * NCHUNK + chunk) * Bn + b_) * OUTn + o_] = acc;
    }
}

// ============================================================================
// kf_v1: v1 = squash(mean_r u_r) per (b,c); seeds g_vcur = v1.
// ============================================================================
__global__ void __launch_bounds__(32)
kf_v1() {
    const int bc = blockIdx.x;
    const int b  = bc >> 5;
    const int c  = bc & 31;
    const int t  = threadIdx.x;

    float acc = 0.f;
    if (t < OUTn) {
        for (int ch = 0; ch < NCHUNK; ch++)
            acc += g_part[(((size_t)c * NCHUNK + ch) * Bn + b) * OUTn + t];
    }
    float val = (t < OUTn) ? acc * (1.0f / Rn) : 0.f;
    float sq = val * val;
    #pragma unroll
    for (int off = 16; off; off >>= 1) sq += __shfl_xor_sync(0xffffffffu, sq, off);
    float coef = (sq / (1.f + sq)) * rsqrtf(sq + 1e-8f);
    float v = val * coef;
    if (t < OUTn) {
        g_v1[(size_t)bc * OUTn + t]   = v;
        g_vcur[(size_t)bc * OUTn + t] = v;
    }
}

// ============================================================================
// k2p: streaming routing pass, o-split across lane pairs. SINGLE-WAVE grid:
// (Cn, 18) = 576 CTAs (<=4/SM resident, no partial second wave — R7's 1152
// CTAs ran 2 waves with a 56%-full tail, capping DRAM at ~71%).
// CTA covers 256 consecutive r of one c; rg halves it (128 r each).
// ============================================================================
__global__ void __launch_bounds__(256)
k2p() {
    const int c     = blockIdx.x;
    const int split = blockIdx.y;           // 0..17, 256 r each
    const int tid   = threadIdx.x;
    const int warp  = tid >> 5;
    const int lane  = tid & 31;
    const int rg    = warp >> 2;            // 0..1 (128 r each)
    const int bq    = warp & 3;             // 0..3
    const int hh    = lane >> 4;            // 0/1 (which 8 outputs)
    const int b     = bq * 16 + (lane & 15);

    __shared__ float sV[Bn * OUTn];
    __shared__ float sRed[2][Bn][18];

    for (int t = tid; t < Bn * OUTn; t += 256) {
        int b_ = t >> 4, o_ = t & 15;
        sV[t] = g_vcur[((size_t)b_ * Cn + c) * OUTn + o_];
    }
    __syncthreads();

    float v[8];
    #pragma unroll
    for (int j = 0; j < 8; j++) v[j] = sV[b * OUTn + hh * 8 + j];

    float d = 0.f;
    float n[8];
    #pragma unroll
    for (int j = 0; j < 8; j++) n[j] = 0.f;

    const int rbase = split * RPASS + rg * 128;
    size_t base = ((size_t)(c * Rn + rbase) * 2 + hh) * Bn + b;

    #pragma unroll 8
    for (int k = 0; k < 128; k++) {
        uint4 q = g_uhat4[base + (size_t)k * 2 * Bn];
        union { __half2 h[4]; uint4 q4; } cv;
        cv.q4 = q;
        float u[8];
        #pragma unroll
        for (int j = 0; j < 4; j++) {
            float2 f = __half22float2(cv.h[j]);
            u[2 * j]     = f.x;
            u[2 * j + 1] = f.y;
        }
        float t = 0.f;
        #pragma unroll
        for (int j = 0; j < 8; j++) t = fmaf(u[j], v[j], t);
        t += __shfl_xor_sync(0xffffffffu, t, 16);       // full 16-dim dot
        float e = __expf(t);
        d += e;
        #pragma unroll
        for (int j = 0; j < 8; j++) n[j] = fmaf(e, u[j], n[j]);
    }

    #pragma unroll
    for (int j = 0; j < 8; j++) sRed[rg][b][hh * 8 + j] = n[j];
    if (hh == 0) sRed[rg][b][16] = d;
    __syncthreads();

    for (int t = tid; t < Bn * 17; t += 256) {
        int b_ = t / 17, o_ = t % 17;
        g_red[(((size_t)c * NSPLIT + split) * Bn + b_) * 17 + o_] =
            sRed[0][b_][o_] + sRed[1][b_][o_];
    }
}

// ============================================================================
// kf_fin: reduce slab partials -> softmax-weighted sum -> squash.
// mode 0: g_vcur = v1 + v2.  mode 1: write v3 to out.
// ============================================================================
__global__ void __launch_bounds__(32)
kf_fin(int mode, float* __restrict__ out) {
    const int bc = blockIdx.x;
    const int b  = bc >> 5;
    const int c  = bc & 31;
    const int t  = threadIdx.x;

    float acc = 0.f;
    if (t < 17) {
        for (int s = 0; s < NSPLIT; s++)
            acc += g_red[(((size_t)c * NSPLIT + s) * Bn + b) * 17 + t];
    }
    float D = __shfl_sync(0xffffffffu, acc, 16);
    float val = (t < OUTn) ? acc / D : 0.f;
    float sq = val * val;
    #pragma unroll
    for (int off = 16; off; off >>= 1) sq += __shfl_xor_sync(0xffffffffu, sq, off);
    float coef = (sq / (1.f + sq)) * rsqrtf(sq + 1e-8f);
    float v = val * coef;
    if (t < OUTn) {
        if (mode == 0)
            g_vcur[(size_t)bc * OUTn + t] = g_v1[(size_t)bc * OUTn + t] + v;
        else
            out[(size_t)bc * OUTn + t] = v;
    }
}

// ============================================================================
extern "C" void kernel_launch(void* const* d_in, const int* in_sizes, int n_in,
                              void* d_out, int out_size) {
    const float* x = (const float*)d_in[0];           // (64, 4608, 8)
    const float* w = (const float*)d_in[1];           // (4608, 32, 8, 16)
    float* out = (float*)d_out;                       // (64, 32, 16)

    k0_transpose<<<dim3(Rn * 2 / 32, Bn / 32), dim3(32, 8)>>>((const float4*)x);
    k1_uhat<<<dim3(Cn, NCHUNK), 256>>>(w);
    kf_v1<<<Bn * Cn, 32>>>();
    k2p<<<dim3(Cn, NSPLIT), 256>>>();
    kf_fin<<<Bn * Cn, 32>>>(0, out);
    k2p<<<dim3(Cn, NSPLIT), 256>>>();
    kf_fin<<<Bn * Cn, 32>>>(1, out);
}

// round 13
// speedup vs baseline: 1.0630x; 1.0094x over previous
#include <cuda_runtime.h>
#include <cuda_fp16.h>

// Problem constants
#define Bn   64
#define Rn   4608
#define Cn   32
#define INn  8
#define OUTn 16
#define RCHUNK 64
#define NCHUNK 72    // Rn / RCHUNK
#define RPASS  256
#define NSPLIT 18    // Rn / RPASS

typedef unsigned long long ull;

// Scratch (device globals; allocation-free per harness rules)
// u_hat layout: [c][r][h(2)][b(64)] of uint4 (8 fp16 each) -> dense 512B warp accesses
static __device__ uint4  g_uhat4[(size_t)Cn * Rn * 2 * Bn];          // 302 MB
static __device__ float4 g_xT4[(size_t)Rn * 2 * Bn];                 // x transposed: [r][h][b] float4
static __device__ float  g_part[(size_t)Cn * NCHUNK * Bn * OUTn];    // iter-1 partial sums (exact fp32)
static __device__ float  g_red[(size_t)Cn * NSPLIT * Bn * 17];       // pass partials (n[16], d)
static __device__ float  g_v1[(size_t)Bn * Cn * OUTn];
static __device__ float  g_vcur[(size_t)Bn * Cn * OUTn];             // current logit vector

// ---- packed f32x2 helpers ----
__device__ __forceinline__ ull pk2(float lo, float hi) {
    ull r;
    asm("mov.b64 %0, {%1, %2};" : "=l"(r) : "f"(lo), "f"(hi));
    return r;
}
__device__ __forceinline__ ull ffma2(ull a, ull b, ull c) {
    ull d;
    asm("fma.rn.f32x2 %0, %1, %2, %3;" : "=l"(d) : "l"(a), "l"(b), "l"(c));
    return d;
}
__device__ __forceinline__ ull fadd2(ull a, ull b) {
    ull d;
    asm("add.rn.f32x2 %0, %1, %2;" : "=l"(d) : "l"(a), "l"(b));
    return d;
}
__device__ __forceinline__ float2 upk2(ull v) {
    float lo, hi;
    asm("mov.b64 {%0, %1}, %2;" : "=f"(lo), "=f"(hi) : "l"(v));
    return make_float2(lo, hi);
}

// ============================================================================
// k0: transpose x (64 b, 9216 float4-cols) -> xT (9216 rows, 64 b).
// ============================================================================
__global__ void __launch_bounds__(256)
k0_transpose(const float4* __restrict__ x4) {
    __shared__ float4 tile[32][33];
    const int f0 = blockIdx.x * 32;
    const int b0 = blockIdx.y * 32;
    const int tx = threadIdx.x;
    const int ty0 = threadIdx.y;
    #pragma unroll
    for (int j = 0; j < 4; j++) {
        int ty = ty0 * 4 + j;
        tile[ty][tx] = x4[(size_t)(b0 + ty) * (Rn * 2) + f0 + tx];
    }
    __syncthreads();
    #pragma unroll
    for (int j = 0; j < 4; j++) {
        int ty = ty0 * 4 + j;
        g_xT4[(size_t)(f0 + ty) * Bn + b0 + tx] = tile[tx][ty];
    }
}

// ============================================================================
// k1: u_hat fp16 (dense) + exact fp32 iter-1 partials. 2-BATCH BLOCKED
// (R7 measured-best structure) + x PREFETCH: next iteration's four float4
// x-loads (L2-resident, ~250 cyc) are issued at the top of the body, before
// the current iteration's LDS/FFMA2 chain (~400 cyc of independent work).
// ============================================================================
__global__ void __launch_bounds__(256)
k1_uhat(const float* __restrict__ w) {
    const int c     = blockIdx.x;
    const int chunk = blockIdx.y;
    const int r0    = chunk * RCHUNK;
    const int tid   = threadIdx.x;
    const int warp  = tid >> 5;        // rgroup 0..7 (8 routes each)
    const int lane  = tid & 31;        // b0 = lane, b1 = lane + 32

    __shared__ float sW[RCHUNK * 128];   // 32 KB; reused for the reduction

    {
        const float4* wg = reinterpret_cast<const float4*>(w);
        float4*       ws = reinterpret_cast<float4*>(sW);
        #pragma unroll
        for (int t = tid; t < RCHUNK * 32; t += 256) {
            int rr = t >> 5;
            int q  = t & 31;
            ws[rr * 32 + q] = wg[((size_t)(r0 + rr) * Cn + c) * 32 + q];
        }
    }
    __syncthreads();

    ull sacc0[8], sacc1[8];            // packed f32x2 iter-1 accumulators
    #pragma unroll
    for (int j = 0; j < 8; j++) { sacc0[j] = 0ull; sacc1[j] = 0ull; }

    // prefetch x for k = 0
    const int rfirst = r0 + warp * 8;
    float4 pxa0 = g_xT4[((size_t)rfirst * 2 + 0) * Bn + lane];
    float4 pxb0 = g_xT4[((size_t)rfirst * 2 + 1) * Bn + lane];
    float4 pxa1 = g_xT4[((size_t)rfirst * 2 + 0) * Bn + lane + 32];
    float4 pxb1 = g_xT4[((size_t)rfirst * 2 + 1) * Bn + lane + 32];

    for (int k = 0; k < 8; k++) {
        const int rr = warp * 8 + k;
        const int r  = r0 + rr;

        // consume prefetched x
        float xv0[8] = {pxa0.x, pxa0.y, pxa0.z, pxa0.w, pxb0.x, pxb0.y, pxb0.z, pxb0.w};
        float xv1[8] = {pxa1.x, pxa1.y, pxa1.z, pxa1.w, pxb1.x, pxb1.y, pxb1.z, pxb1.w};

        // issue next iteration's x loads NOW (hidden behind the FFMA chain)
        if (k < 7) {
            const int rn = r + 1;
            pxa0 = g_xT4[((size_t)rn * 2 + 0) * Bn + lane];
            pxb0 = g_xT4[((size_t)rn * 2 + 1) * Bn + lane];
            pxa1 = g_xT4[((size_t)rn * 2 + 0) * Bn + lane + 32];
            pxb1 = g_xT4[((size_t)rn * 2 + 1) * Bn + lane + 32];
        }

        ull acc0[8], acc1[8];
        #pragma unroll
        for (int j = 0; j < 8; j++) { acc0[j] = 0ull; acc1[j] = 0ull; }

        const ull* wr = reinterpret_cast<const ull*>(sW + rr * 128);
        #pragma unroll
        for (int i = 0; i < 8; i++) {
            ull x20 = pk2(xv0[i], xv0[i]);
            ull x21 = pk2(xv1[i], xv1[i]);
            #pragma unroll
            for (int j = 0; j < 8; j++) {
                ull wv = wr[i * 8 + j];            // broadcast LDS.64, reused 2x
                acc0[j] = ffma2(x20, wv, acc0[j]);
                acc1[j] = ffma2(x21, wv, acc1[j]);
            }
        }

        union { __half2 h[8]; uint4 q[2]; } cv0, cv1;
        #pragma unroll
        for (int j = 0; j < 8; j++) {
            sacc0[j] = fadd2(sacc0[j], acc0[j]);
            sacc1[j] = fadd2(sacc1[j], acc1[j]);
            float2 u0 = upk2(acc0[j]);
            float2 u1 = upk2(acc1[j]);
            cv0.h[j] = __floats2half2_rn(u0.x, u0.y);
            cv1.h[j] = __floats2half2_rn(u1.x, u1.y);
        }
        // dense stores: [c][r][h][b]
        size_t base = ((size_t)(c * Rn + r) * 2) * Bn + lane;
        g_uhat4[base]           = cv0.q[0];
        g_uhat4[base + Bn]      = cv0.q[1];
        g_uhat4[base + 32]      = cv1.q[0];
        g_uhat4[base + Bn + 32] = cv1.q[1];
    }

    // ---- reduce iter-1 partials over the 8 rgroups (fixed order) ----
    __syncthreads();                    // done with sW contents
    float* sred = sW;                   // [8 rg][64 b][16 o] = 32 KB
    #pragma unroll
    for (int j = 0; j < 8; j++) {
        float2 u0 = upk2(sacc0[j]);
        float2 u1 = upk2(sacc1[j]);
        sred[((size_t)warp * Bn + lane) * OUTn + 2 * j]          = u0.x;
        sred[((size_t)warp * Bn + lane) * OUTn + 2 * j + 1]      = u0.y;
        sred[((size_t)warp * Bn + lane + 32) * OUTn + 2 * j]     = u1.x;
        sred[((size_t)warp * Bn + lane + 32) * OUTn + 2 * j + 1] = u1.y;
    }
    __syncthreads();
    #pragma unroll
    for (int s = 0; s < 4; s++) {
        int idx = tid * 4 + s;
        int b_ = idx >> 4, o_ = idx & 15;
        float acc = 0.f;
        #pragma unroll
        for (int rg = 0; rg < 8; rg++)
            acc += sred[((size_t)rg * Bn + b_) * OUTn + o_];
        g_part[(((size_t)c * NCHUNK + chunk) * Bn + b_) * OUTn + o_] = acc;
    }
}

// ============================================================================
// kf_v1: v1 = squash(mean_r u_r) per (b,c); seeds g_vcur = v1.
// ============================================================================
__global__ void __launch_bounds__(32)
kf_v1() {
    const int bc = blockIdx.x;
    const int b  = bc >> 5;
    const int c  = bc & 31;
    const int t  = threadIdx.x;

    float acc = 0.f;
    if (t < OUTn) {
        for (int ch = 0; ch < NCHUNK; ch++)
            acc += g_part[(((size_t)c * NCHUNK + ch) * Bn + b) * OUTn + t];
    }
    float val = (t < OUTn) ? acc * (1.0f / Rn) : 0.f;
    float sq = val * val;
    #pragma unroll
    for (int off = 16; off; off >>= 1) sq += __shfl_xor_sync(0xffffffffu, sq, off);
    float coef = (sq / (1.f + sq)) * rsqrtf(sq + 1e-8f);
    float v = val * coef;
    if (t < OUTn) {
        g_v1[(size_t)bc * OUTn + t]   = v;
        g_vcur[(size_t)bc * OUTn + t] = v;
    }
}

// ============================================================================
// k2p (exact R12 body, measured 51.9us / DRAM 74.4%): streaming routing
// pass, o-split across lane pairs, single-wave grid (Cn, 18).
// ============================================================================
__global__ void __launch_bounds__(256)
k2p() {
    const int c     = blockIdx.x;
    const int split = blockIdx.y;           // 0..17, 256 r each
    const int tid   = threadIdx.x;
    const int warp  = tid >> 5;
    const int lane  = tid & 31;
    const int rg    = warp >> 2;            // 0..1 (128 r each)
    const int bq    = warp & 3;             // 0..3
    const int hh    = lane >> 4;            // 0/1 (which 8 outputs)
    const int b     = bq * 16 + (lane & 15);

    __shared__ float sV[Bn * OUTn];
    __shared__ float sRed[2][Bn][18];

    for (int t = tid; t < Bn * OUTn; t += 256) {
        int b_ = t >> 4, o_ = t & 15;
        sV[t] = g_vcur[((size_t)b_ * Cn + c) * OUTn + o_];
    }
    __syncthreads();

    float v[8];
    #pragma unroll
    for (int j = 0; j < 8; j++) v[j] = sV[b * OUTn + hh * 8 + j];

    float d = 0.f;
    float n[8];
    #pragma unroll
    for (int j = 0; j < 8; j++) n[j] = 0.f;

    const int rbase = split * RPASS + rg * 128;
    size_t base = ((size_t)(c * Rn + rbase) * 2 + hh) * Bn + b;

    #pragma unroll 8
    for (int k = 0; k < 128; k++) {
        uint4 q = g_uhat4[base + (size_t)k * 2 * Bn];
        union { __half2 h[4]; uint4 q4; } cv;
        cv.q4 = q;
        float u[8];
        #pragma unroll
        for (int j = 0; j < 4; j++) {
            float2 f = __half22float2(cv.h[j]);
            u[2 * j]     = f.x;
            u[2 * j + 1] = f.y;
        }
        float t = 0.f;
        #pragma unroll
        for (int j = 0; j < 8; j++) t = fmaf(u[j], v[j], t);
        t += __shfl_xor_sync(0xffffffffu, t, 16);       // full 16-dim dot
        float e = __expf(t);
        d += e;
        #pragma unroll
        for (int j = 0; j < 8; j++) n[j] = fmaf(e, u[j], n[j]);
    }

    #pragma unroll
    for (int j = 0; j < 8; j++) sRed[rg][b][hh * 8 + j] = n[j];
    if (hh == 0) sRed[rg][b][16] = d;
    __syncthreads();

    for (int t = tid; t < Bn * 17; t += 256) {
        int b_ = t / 17, o_ = t % 17;
        g_red[(((size_t)c * NSPLIT + split) * Bn + b_) * 17 + o_] =
            sRed[0][b_][o_] + sRed[1][b_][o_];
    }
}

// ============================================================================
// kf_fin: reduce slab partials -> softmax-weighted sum -> squash.
// mode 0: g_vcur = v1 + v2.  mode 1: write v3 to out.
// ============================================================================
__global__ void __launch_bounds__(32)
kf_fin(int mode, float* __restrict__ out) {
    const int bc = blockIdx.x;
    const int b  = bc >> 5;
    const int c  = bc & 31;
    const int t  = threadIdx.x;

    float acc = 0.f;
    if (t < 17) {
        for (int s = 0; s < NSPLIT; s++)
            acc += g_red[(((size_t)c * NSPLIT + s) * Bn + b) * 17 + t];
    }
    float D = __shfl_sync(0xffffffffu, acc, 16);
    float val = (t < OUTn) ? acc / D : 0.f;
    float sq = val * val;
    #pragma unroll
    for (int off = 16; off; off >>= 1) sq += __shfl_xor_sync(0xffffffffu, sq, off);
    float coef = (sq / (1.f + sq)) * rsqrtf(sq + 1e-8f);
    float v = val * coef;
    if (t < OUTn) {
        if (mode == 0)
            g_vcur[(size_t)bc * OUTn + t] = g_v1[(size_t)bc * OUTn + t] + v;
        else
            out[(size_t)bc * OUTn + t] = v;
    }
}

// ============================================================================
extern "C" void kernel_launch(void* const* d_in, const int* in_sizes, int n_in,
                              void* d_out, int out_size) {
    const float* x = (const float*)d_in[0];           // (64, 4608, 8)
    const float* w = (const float*)d_in[1];           // (4608, 32, 8, 16)
    float* out = (float*)d_out;                       // (64, 32, 16)

    k0_transpose<<<dim3(Rn * 2 / 32, Bn / 32), dim3(32, 8)>>>((const float4*)x);
    k1_uhat<<<dim3(Cn, NCHUNK), 256>>>(w);
    kf_v1<<<Bn * Cn, 32>>>();
    k2p<<<dim3(Cn, NSPLIT), 256>>>();
    kf_fin<<<Bn * Cn, 32>>>(0, out);
    k2p<<<dim3(Cn, NSPLIT), 256>>>();
    kf_fin<<<Bn * Cn, 32>>>(1, out);
}

// round 14
// speedup vs baseline: 1.0665x; 1.0033x over previous
#include <cuda_runtime.h>
#include <cuda_fp16.h>

// Problem constants
#define Bn   64
#define Rn   4608
#define Cn   32
#define INn  8
#define OUTn 16
#define RCHUNK 64
#define NCHUNK 72    // Rn / RCHUNK
#define RPASS  256
#define NSPLIT 18    // Rn / RPASS

typedef unsigned long long ull;

// Scratch (device globals; allocation-free per harness rules)
// u_hat layout: [c][r][h(2)][b(64)] of uint4 (8 fp16 each) -> dense 512B warp accesses
static __device__ uint4  g_uhat4[(size_t)Cn * Rn * 2 * Bn];          // 302 MB
static __device__ float  g_xM[(size_t)Rn * INn * Bn];                // x as [r][i][b] floats (9.4 MB)
static __device__ float  g_part[(size_t)Cn * NCHUNK * Bn * OUTn];    // iter-1 partial sums
static __device__ float  g_red[(size_t)Cn * NSPLIT * Bn * 17];       // pass partials (n[16], d)
static __device__ float  g_v1[(size_t)Bn * Cn * OUTn];
static __device__ float  g_vcur[(size_t)Bn * Cn * OUTn];             // current logit vector

// ---- tf32 / mma helpers ----
__device__ __forceinline__ unsigned tf32(float f) {
    unsigned r;
    asm("cvt.rna.tf32.f32 %0, %1;" : "=r"(r) : "f"(f));
    return r;
}

// D = A(16x8) * B(8x8) + 0     (m16n8k8, tf32 in, f32 out)
__device__ __forceinline__ void mma8_zero(
    float& d0, float& d1, float& d2, float& d3,
    unsigned a0, unsigned a1, unsigned a2, unsigned a3,
    unsigned b0, unsigned b1)
{
    float z = 0.f;
    asm("mma.sync.aligned.m16n8k8.row.col.f32.tf32.tf32.f32 "
        "{%0,%1,%2,%3},{%4,%5,%6,%7},{%8,%9},{%10,%10,%10,%10};"
        : "=f"(d0), "=f"(d1), "=f"(d2), "=f"(d3)
        : "r"(a0), "r"(a1), "r"(a2), "r"(a3), "r"(b0), "r"(b1), "f"(z));
}

// D += A * B   (accumulating form)
__device__ __forceinline__ void mma8_acc(
    float& d0, float& d1, float& d2, float& d3,
    unsigned a0, unsigned a1, unsigned a2, unsigned a3,
    unsigned b0, unsigned b1)
{
    asm("mma.sync.aligned.m16n8k8.row.col.f32.tf32.tf32.f32 "
        "{%0,%1,%2,%3},{%4,%5,%6,%7},{%8,%9},{%0,%1,%2,%3};"
        : "+f"(d0), "+f"(d1), "+f"(d2), "+f"(d3)
        : "r"(a0), "r"(a1), "r"(a2), "r"(a3), "r"(b0), "r"(b1));
}

// ============================================================================
// k0: transpose x (64 b, 9216 float4-cols) -> xM[r][i][b] scalar floats.
// ============================================================================
__global__ void __launch_bounds__(256)
k0_transpose(const float4* __restrict__ x4) {
    __shared__ float4 tile[32][33];
    const int f0 = blockIdx.x * 32;
    const int b0 = blockIdx.y * 32;
    const int tx = threadIdx.x;
    const int ty0 = threadIdx.y;
    #pragma unroll
    for (int j = 0; j < 4; j++) {
        int ty = ty0 * 4 + j;
        tile[ty][tx] = x4[(size_t)(b0 + ty) * (Rn * 2) + f0 + tx];
    }
    __syncthreads();
    #pragma unroll
    for (int j = 0; j < 4; j++) {
        int ty = ty0 * 4 + j;
        float4 v = tile[tx][ty];           // = x4[b0+tx][f0+ty]
        int f = f0 + ty;                   // f = r*2 + h
        size_t base = ((size_t)(f >> 1) * 8 + (f & 1) * 4) * Bn + b0 + tx;
        g_xM[base]            = v.x;       // i = h*4 + 0..3
        g_xM[base + Bn]       = v.y;
        g_xM[base + 2 * Bn]   = v.z;
        g_xM[base + 3 * Bn]   = v.w;
    }
}

// ============================================================================
// k1 (TENSOR-CORE): u_hat fp16 + iter-1 partials via tf32 mma.m16n8k8.
// Grid (Cn, NCHUNK), block 256 = 8 warps; warp handles 8 r, each r as a
// 64x8 @ 8x16 GEMM = 4 m-tiles x 2 n-tiles. W chunk staged (tf32) in smem.
// Each tile issues 2 HMMA: zeroed (store u_r) + accumulating (iter-1 sum).
// ============================================================================
__global__ void __launch_bounds__(256)
k1_uhat(const float* __restrict__ w) {
    const int c     = blockIdx.x;
    const int chunk = blockIdx.y;
    const int r0    = chunk * RCHUNK;
    const int tid   = threadIdx.x;
    const int warp  = tid >> 5;
    const int lane  = tid & 31;
    const int g     = lane >> 2;       // groupID 0..7
    const int t4    = lane & 3;        // thread-in-group 0..3

    __shared__ float sW[RCHUNK * 128];   // 32 KB, tf32-rounded W; reused for reduction

    // Stage W chunk, converting to tf32 (rna) once.
    {
        const float4* wg = reinterpret_cast<const float4*>(w);
        float4*       ws = reinterpret_cast<float4*>(sW);
        for (int t = tid; t < RCHUNK * 32; t += 256) {
            int rr = t >> 5;
            int q  = t & 31;
            float4 v = wg[((size_t)(r0 + rr) * Cn + c) * 32 + q];
            v.x = __uint_as_float(tf32(v.x));
            v.y = __uint_as_float(tf32(v.y));
            v.z = __uint_as_float(tf32(v.z));
            v.w = __uint_as_float(tf32(v.w));
            ws[rr * 32 + q] = v;
        }
    }
    __syncthreads();

    float dacc[4][2][4];               // iter-1 accumulators (mma fragments)
    #pragma unroll
    for (int mi = 0; mi < 4; mi++)
        #pragma unroll
        for (int ni = 0; ni < 2; ni++)
            #pragma unroll
            for (int q = 0; q < 4; q++) dacc[mi][ni][q] = 0.f;

    __half2* gu2 = reinterpret_cast<__half2*>(g_uhat4);

    for (int k = 0; k < 8; k++) {
        const int rr = warp * 8 + k;
        const int r  = r0 + rr;

        // A fragments: x[r][i][b], a0:(g,t4) a1:(g+8,t4) a2:(g,t4+4) a3:(g+8,t4+4)
        const float* xr = g_xM + (size_t)r * (INn * Bn);
        unsigned A[4][4];
        #pragma unroll
        for (int mi = 0; mi < 4; mi++) {
            int bb = mi * 16 + g;
            A[mi][0] = tf32(xr[t4 * Bn + bb]);
            A[mi][1] = tf32(xr[t4 * Bn + bb + 8]);
            A[mi][2] = tf32(xr[(t4 + 4) * Bn + bb]);
            A[mi][3] = tf32(xr[(t4 + 4) * Bn + bb + 8]);
        }

        // B fragments: W[i][o] (k x n, col-major frag): b0:(t4, g+8ni) b1:(t4+4, g+8ni)
        const float* wrow = sW + rr * 128;
        unsigned B[2][2];
        #pragma unroll
        for (int ni = 0; ni < 2; ni++) {
            B[ni][0] = __float_as_uint(wrow[t4 * 16 + ni * 8 + g]);
            B[ni][1] = __float_as_uint(wrow[(t4 + 4) * 16 + ni * 8 + g]);
        }

        #pragma unroll
        for (int mi = 0; mi < 4; mi++) {
            #pragma unroll
            for (int ni = 0; ni < 2; ni++) {
                float d0, d1, d2, d3;
                mma8_zero(d0, d1, d2, d3,
                          A[mi][0], A[mi][1], A[mi][2], A[mi][3],
                          B[ni][0], B[ni][1]);
                mma8_acc(dacc[mi][ni][0], dacc[mi][ni][1], dacc[mi][ni][2], dacc[mi][ni][3],
                         A[mi][0], A[mi][1], A[mi][2], A[mi][3],
                         B[ni][0], B[ni][1]);
                // store: c0:(b=mi*16+g, o=2t4) c1:o+1 c2:(b+8) c3:(b+8,o+1)
                int bb = mi * 16 + g;
                size_t h2 = ((size_t)(c * Rn + r) * 2 + ni) * 256 + bb * 4 + t4;
                gu2[h2]      = __floats2half2_rn(d0, d1);
                gu2[h2 + 32] = __floats2half2_rn(d2, d3);   // b+8 -> +8*4 half2
            }
        }
    }

    // ---- reduce iter-1 partials across the 8 warps (fixed order) ----
    __syncthreads();                    // done with sW contents
    float* sred = sW;                   // [8 warp][64 b][16 o] = 32 KB
    #pragma unroll
    for (int mi = 0; mi < 4; mi++) {
        #pragma unroll
        for (int ni = 0; ni < 2; ni++) {
            int bb = mi * 16 + g;
            int oo = ni * 8 + 2 * t4;
            float* p = sred + ((size_t)warp * Bn + bb) * OUTn + oo;
            p[0]   = dacc[mi][ni][0];
            p[1]   = dacc[mi][ni][1];
            p[128] = dacc[mi][ni][2];   // b+8 -> +8*16 floats
            p[129] = dacc[mi][ni][3];
        }
    }
    __syncthreads();
    #pragma unroll
    for (int s = 0; s < 4; s++) {
        int idx = tid * 4 + s;
        int b_ = idx >> 4, o_ = idx & 15;
        float acc = 0.f;
        #pragma unroll
        for (int wg_ = 0; wg_ < 8; wg_++)
            acc += sred[((size_t)wg_ * Bn + b_) * OUTn + o_];
        g_part[(((size_t)c * NCHUNK + chunk) * Bn + b_) * OUTn + o_] = acc;
    }
}

// ============================================================================
// kf_v1: v1 = squash(mean_r u_r) per (b,c); seeds g_vcur = v1.
// ============================================================================
__global__ void __launch_bounds__(32)
kf_v1() {
    const int bc = blockIdx.x;
    const int b  = bc >> 5;
    const int c  = bc & 31;
    const int t  = threadIdx.x;

    float acc = 0.f;
    if (t < OUTn) {
        for (int ch = 0; ch < NCHUNK; ch++)
            acc += g_part[(((size_t)c * NCHUNK + ch) * Bn + b) * OUTn + t];
    }
    float val = (t < OUTn) ? acc * (1.0f / Rn) : 0.f;
    float sq = val * val;
    #pragma unroll
    for (int off = 16; off; off >>= 1) sq += __shfl_xor_sync(0xffffffffu, sq, off);
    float coef = (sq / (1.f + sq)) * rsqrtf(sq + 1e-8f);
    float v = val * coef;
    if (t < OUTn) {
        g_v1[(size_t)bc * OUTn + t]   = v;
        g_vcur[(size_t)bc * OUTn + t] = v;
    }
}

// ============================================================================
// k2p (exact R12 body, measured 51.9us / DRAM 74.4%): streaming routing
// pass, o-split across lane pairs, single-wave grid (Cn, 18).
// ============================================================================
__global__ void __launch_bounds__(256)
k2p() {
    const int c     = blockIdx.x;
    const int split = blockIdx.y;           // 0..17, 256 r each
    const int tid   = threadIdx.x;
    const int warp  = tid >> 5;
    const int lane  = tid & 31;
    const int rg    = warp >> 2;            // 0..1 (128 r each)
    const int bq    = warp & 3;             // 0..3
    const int hh    = lane >> 4;            // 0/1 (which 8 outputs)
    const int b     = bq * 16 + (lane & 15);

    __shared__ float sV[Bn * OUTn];
    __shared__ float sRed[2][Bn][18];

    for (int t = tid; t < Bn * OUTn; t += 256) {
        int b_ = t >> 4, o_ = t & 15;
        sV[t] = g_vcur[((size_t)b_ * Cn + c) * OUTn + o_];
    }
    __syncthreads();

    float v[8];
    #pragma unroll
    for (int j = 0; j < 8; j++) v[j] = sV[b * OUTn + hh * 8 + j];

    float d = 0.f;
    float n[8];
    #pragma unroll
    for (int j = 0; j < 8; j++) n[j] = 0.f;

    const int rbase = split * RPASS + rg * 128;
    size_t base = ((size_t)(c * Rn + rbase) * 2 + hh) * Bn + b;

    #pragma unroll 8
    for (int k = 0; k < 128; k++) {
        uint4 q = g_uhat4[base + (size_t)k * 2 * Bn];
        union { __half2 h[4]; uint4 q4; } cv;
        cv.q4 = q;
        float u[8];
        #pragma unroll
        for (int j = 0; j < 4; j++) {
            float2 f = __half22float2(cv.h[j]);
            u[2 * j]     = f.x;
            u[2 * j + 1] = f.y;
        }
        float t = 0.f;
        #pragma unroll
        for (int j = 0; j < 8; j++) t = fmaf(u[j], v[j], t);
        t += __shfl_xor_sync(0xffffffffu, t, 16);       // full 16-dim dot
        float e = __expf(t);
        d += e;
        #pragma unroll
        for (int j = 0; j < 8; j++) n[j] = fmaf(e, u[j], n[j]);
    }

    #pragma unroll
    for (int j = 0; j < 8; j++) sRed[rg][b][hh * 8 + j] = n[j];
    if (hh == 0) sRed[rg][b][16] = d;
    __syncthreads();

    for (int t = tid; t < Bn * 17; t += 256) {
        int b_ = t / 17, o_ = t % 17;
        g_red[(((size_t)c * NSPLIT + split) * Bn + b_) * 17 + o_] =
            sRed[0][b_][o_] + sRed[1][b_][o_];
    }
}

// ============================================================================
// kf_fin: reduce slab partials -> softmax-weighted sum -> squash.
// mode 0: g_vcur = v1 + v2.  mode 1: write v3 to out.
// ============================================================================
__global__ void __launch_bounds__(32)
kf_fin(int mode, float* __restrict__ out) {
    const int bc = blockIdx.x;
    const int b  = bc >> 5;
    const int c  = bc & 31;
    const int t  = threadIdx.x;

    float acc = 0.f;
    if (t < 17) {
        for (int s = 0; s < NSPLIT; s++)
            acc += g_red[(((size_t)c * NSPLIT + s) * Bn + b) * 17 + t];
    }
    float D = __shfl_sync(0xffffffffu, acc, 16);
    float val = (t < OUTn) ? acc / D : 0.f;
    float sq = val * val;
    #pragma unroll
    for (int off = 16; off; off >>= 1) sq += __shfl_xor_sync(0xffffffffu, sq, off);
    float coef = (sq / (1.f + sq)) * rsqrtf(sq + 1e-8f);
    float v = val * coef;
    if (t < OUTn) {
        if (mode == 0)
            g_vcur[(size_t)bc * OUTn + t] = g_v1[(size_t)bc * OUTn + t] + v;
        else
            out[(size_t)bc * OUTn + t] = v;
    }
}

// ============================================================================
extern "C" void kernel_launch(void* const* d_in, const int* in_sizes, int n_in,
                              void* d_out, int out_size) {
    const float* x = (const float*)d_in[0];           // (64, 4608, 8)
    const float* w = (const float*)d_in[1];           // (4608, 32, 8, 16)
    float* out = (float*)d_out;                       // (64, 32, 16)

    k0_transpose<<<dim3(Rn * 2 / 32, Bn / 32), dim3(32, 8)>>>((const float4*)x);
    k1_uhat<<<dim3(Cn, NCHUNK), 256>>>(w);
    kf_v1<<<Bn * Cn, 32>>>();
    k2p<<<dim3(Cn, NSPLIT), 256>>>();
    kf_fin<<<Bn * Cn, 32>>>(0, out);
    k2p<<<dim3(Cn, NSPLIT), 256>>>();
    kf_fin<<<Bn * Cn, 32>>>(1, out);
}